// round 4
// baseline (speedup 1.0000x reference)
#include <cuda_runtime.h>
#include <math.h>

// ---------------------------------------------------------------------------
// InteractionPredictor: e3nn-style equivariant GNN, fully fused fp32.
// node irreps: 16x0e + 8x1o (40 floats). Two message-passing steps, then a
// ligand/receptor tensor-product readout -> [EI, 8].
//
// Fusion: per-edge TP weights w = h @ W1 (576 or 2560 wide) are never
// materialized; the TP contraction is folded into the GEMV epilogue.
// ---------------------------------------------------------------------------

#define TB     128
#define NF     40
#define NMAX   16384
#define EIMAX  65536

__device__ float g_node[NMAX * NF];
__device__ float g_msgs[NMAX * NF];
__device__ float g_lig [EIMAX * NF];

#define C24    0.20412414523193154f   /* sqrt(1/24)  path weight (both irreps) */
#define C24S3  0.35355339059327373f   /* sqrt(3)/sqrt(24) = sqrt(1/8)          */
#define INVS3  0.57735026918962576f   /* 1/sqrt(3)                              */
#define PWREC  0.05590169943749474f   /* 1/sqrt(320)                            */
#define DEMBC  8.4335731f             /* 1.14136 * e^2 (sqrt(20) folds into MLP)*/
#define INV32  0.17677669529663687f   /* 1/sqrt(32)                             */

__device__ __forceinline__ float siluN(float x) {
    // jax.nn.silu(x) * normalize2mom(silu)
    return x * (1.0f / (1.0f + __expf(-x))) * 1.6789717f;
}

// ---------------------------------------------------------------------------
// zero the message accumulator
// ---------------------------------------------------------------------------
__global__ void k_zero_msgs(int n) {
    int i = blockIdx.x * blockDim.x + threadIdx.x;
    if (i < n) g_msgs[i] = 0.0f;
}

// ---------------------------------------------------------------------------
// node embedding: node_s = mlp(x; emb_w0[A,64], emb_w1[64,16]); geo part = 0
// ---------------------------------------------------------------------------
__global__ void k_embed(const float* __restrict__ x, int N, int A,
                        const float* __restrict__ W0, const float* __restrict__ W1) {
    int n = blockIdx.x * blockDim.x + threadIdx.x;
    if (n >= N) return;
    float inv = rsqrtf((float)A);
    float a[16];
#pragma unroll
    for (int b = 0; b < 16; b++) a[b] = (b < A) ? x[n * A + b] : 0.0f;
    float h[64];
#pragma unroll 4
    for (int k = 0; k < 64; k++) {
        float s = 0.0f;
#pragma unroll
        for (int b = 0; b < 16; b++)
            if (b < A) s += a[b] * W0[b * 64 + k];
        h[k] = siluN(s * inv) * 0.125f;     // 0.125 = 1/sqrt(64) of layer 2
    }
    float* nr = g_node + n * NF;
#pragma unroll
    for (int w = 0; w < 16; w++) {
        float s = 0.0f;
#pragma unroll 8
        for (int k = 0; k < 64; k++) s += h[k] * W1[k * 16 + w];
        nr[w] = s;
    }
#pragma unroll
    for (int t = 0; t < 24; t++) nr[16 + t] = 0.0f;
}

// ---------------------------------------------------------------------------
// node update: scal = mlp([msgs_s*scale, node_s]); geo = (msgs_g*scale+node_g)*gmul
// ---------------------------------------------------------------------------
__global__ void k_update(int N, const float* __restrict__ imp, float degf,
                         const float* __restrict__ W0, const float* __restrict__ W1,
                         float gmul) {
    int n = blockIdx.x * blockDim.x + threadIdx.x;
    if (n >= N) return;
    float scale = imp[0] * rsqrtf(degf);
    float* nr = g_node + n * NF;
    const float* mr = g_msgs + n * NF;
    float a[32];
#pragma unroll
    for (int t = 0; t < 16; t++) a[t] = mr[t] * scale;
#pragma unroll
    for (int t = 0; t < 16; t++) a[16 + t] = nr[t];
    float h[64];
#pragma unroll 2
    for (int k = 0; k < 64; k++) {
        float s = 0.0f;
#pragma unroll
        for (int b = 0; b < 32; b++) s += a[b] * W0[b * 64 + k];
        h[k] = siluN(s * INV32) * 0.125f;
    }
    float sc[16];
#pragma unroll
    for (int w = 0; w < 16; w++) {
        float s = 0.0f;
#pragma unroll 8
        for (int k = 0; k < 64; k++) s += h[k] * W1[k * 16 + w];
        sc[w] = s;
    }
    float ge[24];
#pragma unroll
    for (int t = 0; t < 24; t++) ge[t] = (mr[16 + t] * scale + nr[16 + t]) * gmul;
#pragma unroll
    for (int w = 0; w < 16; w++) nr[w] = sc[w];
#pragma unroll
    for (int t = 0; t < 24; t++) nr[16 + t] = ge[t];
}

// ---------------------------------------------------------------------------
// TP (Sx0e+Vx1o) x (1x0e+1x1o) -> (Sx0e+Vx1o) with fused weight GEMV.
//   out_s[w] = C24 * ( sum_u xs[u] wA[u][w] + sum_u (xv_u . r) wB[u][w] )
//   out_v[w][i] = C24 * ( sqrt3 * r[i] * sum_u xs[u] wC[u][w] + sum_u xv[u][i] wD[u][w] )
// where w*[u][w] = sum_k h[k] W1[k][block offset]. h is in smem (incl *0.125).
// ---------------------------------------------------------------------------
__device__ __forceinline__ void tp_node_sh(
    const float* __restrict__ shcol,            // h column, stride TB
    const float* __restrict__ nrow,             // node features (40 floats)
    float r0, float r1, float r2,
    const float* __restrict__ W1,               // [64, 576] row-major
    float* __restrict__ os, float* __restrict__ ov)
{
#pragma unroll
    for (int t = 0; t < 16; t++) os[t] = 0.0f;
#pragma unroll
    for (int t = 0; t < 24; t++) ov[t] = 0.0f;

    // Block A: 0e x 0e -> 0e ; cols [u*16, u*16+16), u<16
#pragma unroll 1
    for (int u = 0; u < 16; u++) {
        float w16[16];
#pragma unroll
        for (int t = 0; t < 16; t++) w16[t] = 0.0f;
        const float* base = W1 + u * 16;
#pragma unroll 4
        for (int k = 0; k < 64; k++) {
            float hk = shcol[k * TB];
            const float4* p = reinterpret_cast<const float4*>(base + k * 576);
            float4 q0 = __ldg(p), q1 = __ldg(p + 1), q2 = __ldg(p + 2), q3 = __ldg(p + 3);
            w16[0]  += hk * q0.x; w16[1]  += hk * q0.y; w16[2]  += hk * q0.z; w16[3]  += hk * q0.w;
            w16[4]  += hk * q1.x; w16[5]  += hk * q1.y; w16[6]  += hk * q1.z; w16[7]  += hk * q1.w;
            w16[8]  += hk * q2.x; w16[9]  += hk * q2.y; w16[10] += hk * q2.z; w16[11] += hk * q2.w;
            w16[12] += hk * q3.x; w16[13] += hk * q3.y; w16[14] += hk * q3.z; w16[15] += hk * q3.w;
        }
        float cf = C24 * __ldg(nrow + u);
#pragma unroll
        for (int t = 0; t < 16; t++) os[t] += cf * w16[t];
    }

    // Block B: 1o x 1o -> 0e ; cols [256+u*16, ...), u<8 ; coef C24*(xv_u . r)
#pragma unroll 1
    for (int u = 0; u < 8; u++) {
        float w16[16];
#pragma unroll
        for (int t = 0; t < 16; t++) w16[t] = 0.0f;
        const float* base = W1 + 256 + u * 16;
#pragma unroll 4
        for (int k = 0; k < 64; k++) {
            float hk = shcol[k * TB];
            const float4* p = reinterpret_cast<const float4*>(base + k * 576);
            float4 q0 = __ldg(p), q1 = __ldg(p + 1), q2 = __ldg(p + 2), q3 = __ldg(p + 3);
            w16[0]  += hk * q0.x; w16[1]  += hk * q0.y; w16[2]  += hk * q0.z; w16[3]  += hk * q0.w;
            w16[4]  += hk * q1.x; w16[5]  += hk * q1.y; w16[6]  += hk * q1.z; w16[7]  += hk * q1.w;
            w16[8]  += hk * q2.x; w16[9]  += hk * q2.y; w16[10] += hk * q2.z; w16[11] += hk * q2.w;
            w16[12] += hk * q3.x; w16[13] += hk * q3.y; w16[14] += hk * q3.z; w16[15] += hk * q3.w;
        }
        float cf = C24 * (__ldg(nrow + 16 + u * 3) * r0 +
                          __ldg(nrow + 17 + u * 3) * r1 +
                          __ldg(nrow + 18 + u * 3) * r2);
#pragma unroll
        for (int t = 0; t < 16; t++) os[t] += cf * w16[t];
    }

    // Block C: 0e x 1o -> 1o ; cols [384+u*8, ...), u<16
#pragma unroll 1
    for (int u = 0; u < 16; u++) {
        float w8[8];
#pragma unroll
        for (int t = 0; t < 8; t++) w8[t] = 0.0f;
        const float* base = W1 + 384 + u * 8;
#pragma unroll 4
        for (int k = 0; k < 64; k++) {
            float hk = shcol[k * TB];
            const float4* p = reinterpret_cast<const float4*>(base + k * 576);
            float4 q0 = __ldg(p), q1 = __ldg(p + 1);
            w8[0] += hk * q0.x; w8[1] += hk * q0.y; w8[2] += hk * q0.z; w8[3] += hk * q0.w;
            w8[4] += hk * q1.x; w8[5] += hk * q1.y; w8[6] += hk * q1.z; w8[7] += hk * q1.w;
        }
        float cf = C24S3 * __ldg(nrow + u);
#pragma unroll
        for (int t = 0; t < 8; t++) {
            float s = cf * w8[t];
            ov[t * 3 + 0] += s * r0;
            ov[t * 3 + 1] += s * r1;
            ov[t * 3 + 2] += s * r2;
        }
    }

    // Block D: 1o x 0e -> 1o ; cols [512+u*8, ...), u<8
#pragma unroll 1
    for (int u = 0; u < 8; u++) {
        float w8[8];
#pragma unroll
        for (int t = 0; t < 8; t++) w8[t] = 0.0f;
        const float* base = W1 + 512 + u * 8;
#pragma unroll 4
        for (int k = 0; k < 64; k++) {
            float hk = shcol[k * TB];
            const float4* p = reinterpret_cast<const float4*>(base + k * 576);
            float4 q0 = __ldg(p), q1 = __ldg(p + 1);
            w8[0] += hk * q0.x; w8[1] += hk * q0.y; w8[2] += hk * q0.z; w8[3] += hk * q0.w;
            w8[4] += hk * q1.x; w8[5] += hk * q1.y; w8[6] += hk * q1.z; w8[7] += hk * q1.w;
        }
        float c0 = C24 * __ldg(nrow + 16 + u * 3);
        float c1 = C24 * __ldg(nrow + 17 + u * 3);
        float c2 = C24 * __ldg(nrow + 18 + u * 3);
#pragma unroll
        for (int t = 0; t < 8; t++) {
            ov[t * 3 + 0] += c0 * w8[t];
            ov[t * 3 + 1] += c1 * w8[t];
            ov[t * 3 + 2] += c2 * w8[t];
        }
    }
}

// ---------------------------------------------------------------------------
// message kernel: per edge, w = mlp(edge_attr), tp with node[src], scatter to dst
// ---------------------------------------------------------------------------
__global__ void __launch_bounds__(TB) k_msg(
    const float* __restrict__ pos,
    const int* __restrict__ srcI, const int* __restrict__ dstI,
    const float* __restrict__ eattr, int E, int B,
    const float* __restrict__ W0, const float* __restrict__ W1)
{
    __shared__ float sh[64 * TB];
    int tid = threadIdx.x;
    int e = blockIdx.x * TB + tid;
    if (e >= E) return;
    float inv = rsqrtf((float)B);
    float a[8];
#pragma unroll
    for (int b = 0; b < 8; b++) a[b] = (b < B) ? eattr[e * B + b] : 0.0f;
    float* shcol = sh + tid;
#pragma unroll 2
    for (int k = 0; k < 64; k++) {
        float s = 0.0f;
#pragma unroll
        for (int b = 0; b < 8; b++)
            if (b < B) s += a[b] * W0[b * 64 + k];
        shcol[k * TB] = siluN(s * inv) * 0.125f;
    }
    int si = srcI[e], di = dstI[e];
    float vx = pos[di * 3 + 0] - pos[si * 3 + 0];
    float vy = pos[di * 3 + 1] - pos[si * 3 + 1];
    float vz = pos[di * 3 + 2] - pos[si * 3 + 2];
    float rn = rsqrtf(vx * vx + vy * vy + vz * vz);
    float os[16], ov[24];
    tp_node_sh(shcol, g_node + si * NF, vx * rn, vy * rn, vz * rn, W1, os, ov);
    float* mr = g_msgs + di * NF;
#pragma unroll
    for (int t = 0; t < 16; t++) atomicAdd(mr + t, os[t]);
#pragma unroll
    for (int t = 0; t < 24; t++) atomicAdd(mr + 16 + t, ov[t]);
}

// ---------------------------------------------------------------------------
// distance embedding: soft_one_hot_linspace(smooth_finite, cutoff)   (20 basis)
// includes the sqrt(20)/sqrt(fan_in) cancellation for the following MLP.
// ---------------------------------------------------------------------------
__device__ __forceinline__ void demb_compute(float d, float* a) {
    float tt = d * 4.2f;                        // d / (RADIUS/(NB+1)) = d*21/5
#pragma unroll
    for (int i = 0; i < 20; i++) {
        float diff = tt - (float)(i + 1);
        float p = diff + 1.0f, q = 1.0f - diff;
        float s1 = (p > 0.0f) ? __expf(-1.0f / p) : 0.0f;
        float s2 = (q > 0.0f) ? __expf(-1.0f / q) : 0.0f;
        a[i] = DEMBC * s1 * s2;
    }
}

// ---------------------------------------------------------------------------
// ligand embedding: lig_emb[e] = tp(node[lig], sh(vec), mlp(demb))
// ---------------------------------------------------------------------------
__global__ void __launch_bounds__(TB) k_lig(
    const float* __restrict__ pos,
    const int* __restrict__ recI, const int* __restrict__ ligI, int EI,
    const float* __restrict__ W0, const float* __restrict__ W1)
{
    __shared__ float sh[64 * TB];
    int tid = threadIdx.x;
    int e = blockIdx.x * TB + tid;
    if (e >= EI) return;
    int ri = recI[e], li = ligI[e];
    float vx = pos[li * 3 + 0] - pos[ri * 3 + 0];
    float vy = pos[li * 3 + 1] - pos[ri * 3 + 1];
    float vz = pos[li * 3 + 2] - pos[ri * 3 + 2];
    float d2 = vx * vx + vy * vy + vz * vz;
    float invd = rsqrtf(d2);
    float d = d2 * invd;
    float a[20];
    demb_compute(d, a);
    float* shcol = sh + tid;
#pragma unroll 2
    for (int k = 0; k < 64; k++) {
        float s = 0.0f;
#pragma unroll
        for (int i = 0; i < 20; i++) s += a[i] * W0[i * 64 + k];
        shcol[k * TB] = siluN(s) * 0.125f;
    }
    float os[16], ov[24];
    tp_node_sh(shcol, g_node + li * NF, vx * invd, vy * invd, vz * invd, W1, os, ov);
    float* lr = g_lig + e * NF;
#pragma unroll
    for (int t = 0; t < 16; t++) lr[t] = os[t];
#pragma unroll
    for (int t = 0; t < 24; t++) lr[16 + t] = ov[t];
}

// ---------------------------------------------------------------------------
// receptor TP readout: out[e][o] = pw*( sum_uv ls[u] rs[v] w1[u,v,o]
//                                       + (1/sqrt3) sum_uv (lv_u . rv_v) w2[u,v,o] )
// ---------------------------------------------------------------------------
__global__ void __launch_bounds__(TB) k_rec(
    const float* __restrict__ pos,
    const int* __restrict__ recI, const int* __restrict__ ligI, int EI,
    const float* __restrict__ W0, const float* __restrict__ W1,
    float* __restrict__ out)
{
    __shared__ float sh[64 * TB];
    int tid = threadIdx.x;
    int e = blockIdx.x * TB + tid;
    if (e >= EI) return;
    int ri = recI[e], li = ligI[e];
    float vx = pos[li * 3 + 0] - pos[ri * 3 + 0];
    float vy = pos[li * 3 + 1] - pos[ri * 3 + 1];
    float vz = pos[li * 3 + 2] - pos[ri * 3 + 2];
    float d2 = vx * vx + vy * vy + vz * vz;
    float d = d2 * rsqrtf(d2);
    float a[20];
    demb_compute(d, a);
    float* shcol = sh + tid;
#pragma unroll 2
    for (int k = 0; k < 64; k++) {
        float s = 0.0f;
#pragma unroll
        for (int i = 0; i < 20; i++) s += a[i] * W0[i * 64 + k];
        shcol[k * TB] = siluN(s) * 0.125f;
    }
    const float* L = g_lig + e * NF;
    const float* R = g_node + ri * NF;
    float acc[8];
#pragma unroll
    for (int t = 0; t < 8; t++) acc[t] = 0.0f;

    // scalar x scalar -> 8x0e : w1[u][v][o] at (u*16+v)*8
#pragma unroll 1
    for (int u = 0; u < 16; u++) {
        float lu = __ldg(L + u);
#pragma unroll 1
        for (int v = 0; v < 16; v++) {
            float w8[8];
#pragma unroll
            for (int t = 0; t < 8; t++) w8[t] = 0.0f;
            const float* base = W1 + (u * 16 + v) * 8;
#pragma unroll 4
            for (int k = 0; k < 64; k++) {
                float hk = shcol[k * TB];
                const float4* p = reinterpret_cast<const float4*>(base + k * 2560);
                float4 q0 = __ldg(p), q1 = __ldg(p + 1);
                w8[0] += hk * q0.x; w8[1] += hk * q0.y; w8[2] += hk * q0.z; w8[3] += hk * q0.w;
                w8[4] += hk * q1.x; w8[5] += hk * q1.y; w8[6] += hk * q1.z; w8[7] += hk * q1.w;
            }
            float cf = lu * __ldg(R + v);
#pragma unroll
            for (int t = 0; t < 8; t++) acc[t] += cf * w8[t];
        }
    }

    // vector x vector -> 8x0e : w2[u][v][o] at 2048 + (u*8+v)*8, coef (lv.rv)/sqrt3
#pragma unroll 1
    for (int u = 0; u < 8; u++) {
        float l0 = __ldg(L + 16 + u * 3);
        float l1 = __ldg(L + 17 + u * 3);
        float l2 = __ldg(L + 18 + u * 3);
#pragma unroll 1
        for (int v = 0; v < 8; v++) {
            float w8[8];
#pragma unroll
            for (int t = 0; t < 8; t++) w8[t] = 0.0f;
            const float* base = W1 + 2048 + (u * 8 + v) * 8;
#pragma unroll 4
            for (int k = 0; k < 64; k++) {
                float hk = shcol[k * TB];
                const float4* p = reinterpret_cast<const float4*>(base + k * 2560);
                float4 q0 = __ldg(p), q1 = __ldg(p + 1);
                w8[0] += hk * q0.x; w8[1] += hk * q0.y; w8[2] += hk * q0.z; w8[3] += hk * q0.w;
                w8[4] += hk * q1.x; w8[5] += hk * q1.y; w8[6] += hk * q1.z; w8[7] += hk * q1.w;
            }
            float cf = (l0 * __ldg(R + 16 + v * 3) +
                        l1 * __ldg(R + 17 + v * 3) +
                        l2 * __ldg(R + 18 + v * 3)) * INVS3;
#pragma unroll
            for (int t = 0; t < 8; t++) acc[t] += cf * w8[t];
        }
    }

#pragma unroll
    for (int t = 0; t < 8; t++) out[e * 8 + t] = PWREC * acc[t];
}

// ---------------------------------------------------------------------------
// host launcher (graph-capturable: kernel launches only)
// ---------------------------------------------------------------------------
extern "C" void kernel_launch(void* const* d_in, const int* in_sizes, int n_in,
                              void* d_out, int out_size) {
    (void)n_in; (void)out_size;
    const float* x       = (const float*)d_in[0];
    const float* pos     = (const float*)d_in[1];
    const int*   eidx    = (const int*)  d_in[2];
    const float* eattr   = (const float*)d_in[3];
    const int*   iidx    = (const int*)  d_in[4];
    const float* emb_w0  = (const float*)d_in[5];
    const float* emb_w1  = (const float*)d_in[6];
    const float* imp0    = (const float*)d_in[7];
    const float* msg0_w0 = (const float*)d_in[8];
    const float* msg0_w1 = (const float*)d_in[9];
    const float* upd0_w0 = (const float*)d_in[10];
    const float* upd0_w1 = (const float*)d_in[11];
    const float* imp1    = (const float*)d_in[12];
    const float* msg1_w0 = (const float*)d_in[13];
    const float* msg1_w1 = (const float*)d_in[14];
    const float* upd1_w0 = (const float*)d_in[15];
    const float* upd1_w1 = (const float*)d_in[16];
    const float* lig_w0  = (const float*)d_in[17];
    const float* lig_w1  = (const float*)d_in[18];
    const float* rec_w0  = (const float*)d_in[19];
    const float* rec_w1  = (const float*)d_in[20];

    int N  = in_sizes[1] / 3;
    int A  = in_sizes[0] / N;
    int E  = in_sizes[2] / 2;
    int B  = in_sizes[3] / E;
    int EI = in_sizes[4] / 2;
    const int* src  = eidx;
    const int* dst  = eidx + E;
    const int* recI = iidx;
    const int* ligI = iidx + EI;
    float degf = (float)E / (float)N;

    int gn = (N + TB - 1) / TB;
    int ge = (E + TB - 1) / TB;
    int gi = (EI + TB - 1) / TB;
    int gz = (N * NF + 255) / 256;

    k_embed<<<gn, TB>>>(x, N, A, emb_w0, emb_w1);

    // message-passing step 0
    k_zero_msgs<<<gz, 256>>>(N * NF);
    k_msg<<<ge, TB>>>(pos, src, dst, eattr, E, B, msg0_w0, msg0_w1);
    k_update<<<gn, TB>>>(N, imp0, degf, upd0_w0, upd0_w1, 1.0f);

    // message-passing step 1
    k_zero_msgs<<<gz, 256>>>(N * NF);
    k_msg<<<ge, TB>>>(pos, src, dst, eattr, E, B, msg1_w0, msg1_w1);
    k_update<<<gn, TB>>>(N, imp1, degf, upd1_w0, upd1_w1, 0.5f);

    // readout
    k_lig<<<gi, TB>>>(pos, recI, ligI, EI, lig_w0, lig_w1);
    k_rec<<<gi, TB>>>(pos, recI, ligI, EI, rec_w0, rec_w1, (float*)d_out);
}

// round 5
// speedup vs baseline: 1.2945x; 1.2945x over previous
#include <cuda_runtime.h>
#include <math.h>

// ---------------------------------------------------------------------------
// InteractionPredictor: e3nn-style equivariant GNN, fully fused fp32.
// node irreps: 16x0e + 8x1o (40 floats). Two message-passing steps, then a
// ligand/receptor tensor-product readout -> [EI, 8].
//
// R4: warp-cooperative edge tiles. Each 128-thread block handles 32 edges;
// 4 warps split the k=64 hidden dimension (16 k's each). Lanes = edges, so
// all weight loads are warp-uniform broadcasts; per-warp partials reduce
// through shared memory. 4x the eligible warps vs thread-per-edge.
// ---------------------------------------------------------------------------

#define TB     128
#define EPB    32          /* edges per block  */
#define KC     16          /* k-chunk per warp */
#define NF     40
#define NMAX   16384
#define EIMAX  65536

__device__ float g_node[NMAX * NF];
__device__ float g_msgs[NMAX * NF];
__device__ float g_lig [EIMAX * NF];

#define C24    0.20412414523193154f   /* sqrt(1/24)  path weight (both irreps) */
#define C24S3  0.35355339059327373f   /* sqrt(3)/sqrt(24) = sqrt(1/8)          */
#define INVS3  0.57735026918962576f   /* 1/sqrt(3)                              */
#define PWREC  0.05590169943749474f   /* 1/sqrt(320)                            */
#define DEMBC  8.4335731f             /* 1.14136 * e^2 (sqrt(20) folds into MLP)*/
#define INV32  0.17677669529663687f   /* 1/sqrt(32)                             */

__device__ __forceinline__ float siluN(float x) {
    return x * (1.0f / (1.0f + __expf(-x))) * 1.6789717f;
}

// ---------------------------------------------------------------------------
__global__ void k_zero_msgs(int n) {
    int i = blockIdx.x * blockDim.x + threadIdx.x;
    if (i < n) g_msgs[i] = 0.0f;
}

// ---------------------------------------------------------------------------
// node embedding: node_s = mlp(x; emb_w0[A,64], emb_w1[64,16]); geo part = 0
// ---------------------------------------------------------------------------
__global__ void k_embed(const float* __restrict__ x, int N, int A,
                        const float* __restrict__ W0, const float* __restrict__ W1) {
    int n = blockIdx.x * blockDim.x + threadIdx.x;
    if (n >= N) return;
    float inv = rsqrtf((float)A);
    float a[16];
#pragma unroll
    for (int b = 0; b < 16; b++) a[b] = (b < A) ? x[n * A + b] : 0.0f;
    float h[64];
#pragma unroll 4
    for (int k = 0; k < 64; k++) {
        float s = 0.0f;
#pragma unroll
        for (int b = 0; b < 16; b++)
            if (b < A) s += a[b] * W0[b * 64 + k];
        h[k] = siluN(s * inv) * 0.125f;
    }
    float* nr = g_node + n * NF;
#pragma unroll
    for (int w = 0; w < 16; w++) {
        float s = 0.0f;
#pragma unroll 8
        for (int k = 0; k < 64; k++) s += h[k] * W1[k * 16 + w];
        nr[w] = s;
    }
#pragma unroll
    for (int t = 0; t < 24; t++) nr[16 + t] = 0.0f;
}

// ---------------------------------------------------------------------------
// node update
// ---------------------------------------------------------------------------
__global__ void k_update(int N, const float* __restrict__ imp, float degf,
                         const float* __restrict__ W0, const float* __restrict__ W1,
                         float gmul) {
    int n = blockIdx.x * blockDim.x + threadIdx.x;
    if (n >= N) return;
    float scale = imp[0] * rsqrtf(degf);
    float* nr = g_node + n * NF;
    const float* mr = g_msgs + n * NF;
    float a[32];
#pragma unroll
    for (int t = 0; t < 16; t++) a[t] = mr[t] * scale;
#pragma unroll
    for (int t = 0; t < 16; t++) a[16 + t] = nr[t];
    float h[64];
#pragma unroll 2
    for (int k = 0; k < 64; k++) {
        float s = 0.0f;
#pragma unroll
        for (int b = 0; b < 32; b++) s += a[b] * W0[b * 64 + k];
        h[k] = siluN(s * INV32) * 0.125f;
    }
    float sc[16];
#pragma unroll
    for (int w = 0; w < 16; w++) {
        float s = 0.0f;
#pragma unroll 8
        for (int k = 0; k < 64; k++) s += h[k] * W1[k * 16 + w];
        sc[w] = s;
    }
    float ge[24];
#pragma unroll
    for (int t = 0; t < 24; t++) ge[t] = (mr[16 + t] * scale + nr[16 + t]) * gmul;
#pragma unroll
    for (int w = 0; w < 16; w++) nr[w] = sc[w];
#pragma unroll
    for (int t = 0; t < 24; t++) nr[16 + t] = ge[t];
}

// ---------------------------------------------------------------------------
// Warp-cooperative TP fold (one k-chunk of 16).
// shH: h values [64][EPB] (lane = edge), shN: node feats [40][EPB].
// Accumulates one warp's k-partial of the TP into os[16], ov[24].
// ---------------------------------------------------------------------------
__device__ __forceinline__ void tp_fold(
    const float* __restrict__ shH, int lane, int kbase,
    const float* __restrict__ shN,
    float r0, float r1, float r2,
    const float* __restrict__ W1,   // [64, 576] row-major
    float* __restrict__ os, float* __restrict__ ov)
{
#pragma unroll
    for (int t = 0; t < 16; t++) os[t] = 0.0f;
#pragma unroll
    for (int t = 0; t < 24; t++) ov[t] = 0.0f;
    const float* hp = shH + kbase * EPB + lane;
    const float* Wk = W1 + kbase * 576;

    // Block A: 0e x 0e -> 0e ; cols [u*16, +16), u<16
#pragma unroll 1
    for (int u = 0; u < 16; u++) {
        float w16[16];
#pragma unroll
        for (int t = 0; t < 16; t++) w16[t] = 0.0f;
        const float* base = Wk + u * 16;
#pragma unroll 4
        for (int j = 0; j < KC; j++) {
            float hk = hp[j * EPB];
            const float4* p = reinterpret_cast<const float4*>(base + j * 576);
            float4 q0 = __ldg(p), q1 = __ldg(p + 1), q2 = __ldg(p + 2), q3 = __ldg(p + 3);
            w16[0]  += hk * q0.x; w16[1]  += hk * q0.y; w16[2]  += hk * q0.z; w16[3]  += hk * q0.w;
            w16[4]  += hk * q1.x; w16[5]  += hk * q1.y; w16[6]  += hk * q1.z; w16[7]  += hk * q1.w;
            w16[8]  += hk * q2.x; w16[9]  += hk * q2.y; w16[10] += hk * q2.z; w16[11] += hk * q2.w;
            w16[12] += hk * q3.x; w16[13] += hk * q3.y; w16[14] += hk * q3.z; w16[15] += hk * q3.w;
        }
        float cf = C24 * shN[u * EPB + lane];
#pragma unroll
        for (int t = 0; t < 16; t++) os[t] += cf * w16[t];
    }

    // Block B: 1o x 1o -> 0e ; cols [256+u*16, ...), u<8 ; coef C24*(xv_u . r)
#pragma unroll 1
    for (int u = 0; u < 8; u++) {
        float w16[16];
#pragma unroll
        for (int t = 0; t < 16; t++) w16[t] = 0.0f;
        const float* base = Wk + 256 + u * 16;
#pragma unroll 4
        for (int j = 0; j < KC; j++) {
            float hk = hp[j * EPB];
            const float4* p = reinterpret_cast<const float4*>(base + j * 576);
            float4 q0 = __ldg(p), q1 = __ldg(p + 1), q2 = __ldg(p + 2), q3 = __ldg(p + 3);
            w16[0]  += hk * q0.x; w16[1]  += hk * q0.y; w16[2]  += hk * q0.z; w16[3]  += hk * q0.w;
            w16[4]  += hk * q1.x; w16[5]  += hk * q1.y; w16[6]  += hk * q1.z; w16[7]  += hk * q1.w;
            w16[8]  += hk * q2.x; w16[9]  += hk * q2.y; w16[10] += hk * q2.z; w16[11] += hk * q2.w;
            w16[12] += hk * q3.x; w16[13] += hk * q3.y; w16[14] += hk * q3.z; w16[15] += hk * q3.w;
        }
        float cf = C24 * (shN[(16 + u * 3) * EPB + lane] * r0 +
                          shN[(17 + u * 3) * EPB + lane] * r1 +
                          shN[(18 + u * 3) * EPB + lane] * r2);
#pragma unroll
        for (int t = 0; t < 16; t++) os[t] += cf * w16[t];
    }

    // Block C: 0e x 1o -> 1o ; cols [384+u*8, ...), u<16
#pragma unroll 1
    for (int u = 0; u < 16; u++) {
        float w8[8];
#pragma unroll
        for (int t = 0; t < 8; t++) w8[t] = 0.0f;
        const float* base = Wk + 384 + u * 8;
#pragma unroll 4
        for (int j = 0; j < KC; j++) {
            float hk = hp[j * EPB];
            const float4* p = reinterpret_cast<const float4*>(base + j * 576);
            float4 q0 = __ldg(p), q1 = __ldg(p + 1);
            w8[0] += hk * q0.x; w8[1] += hk * q0.y; w8[2] += hk * q0.z; w8[3] += hk * q0.w;
            w8[4] += hk * q1.x; w8[5] += hk * q1.y; w8[6] += hk * q1.z; w8[7] += hk * q1.w;
        }
        float cf = C24S3 * shN[u * EPB + lane];
#pragma unroll
        for (int t = 0; t < 8; t++) {
            float s = cf * w8[t];
            ov[t * 3 + 0] += s * r0;
            ov[t * 3 + 1] += s * r1;
            ov[t * 3 + 2] += s * r2;
        }
    }

    // Block D: 1o x 0e -> 1o ; cols [512+u*8, ...), u<8
#pragma unroll 1
    for (int u = 0; u < 8; u++) {
        float w8[8];
#pragma unroll
        for (int t = 0; t < 8; t++) w8[t] = 0.0f;
        const float* base = Wk + 512 + u * 8;
#pragma unroll 4
        for (int j = 0; j < KC; j++) {
            float hk = hp[j * EPB];
            const float4* p = reinterpret_cast<const float4*>(base + j * 576);
            float4 q0 = __ldg(p), q1 = __ldg(p + 1);
            w8[0] += hk * q0.x; w8[1] += hk * q0.y; w8[2] += hk * q0.z; w8[3] += hk * q0.w;
            w8[4] += hk * q1.x; w8[5] += hk * q1.y; w8[6] += hk * q1.z; w8[7] += hk * q1.w;
        }
        float c0 = C24 * shN[(16 + u * 3) * EPB + lane];
        float c1 = C24 * shN[(17 + u * 3) * EPB + lane];
        float c2 = C24 * shN[(18 + u * 3) * EPB + lane];
#pragma unroll
        for (int t = 0; t < 8; t++) {
            ov[t * 3 + 0] += c0 * w8[t];
            ov[t * 3 + 1] += c1 * w8[t];
            ov[t * 3 + 2] += c2 * w8[t];
        }
    }
}

// ---------------------------------------------------------------------------
// distance embedding (per lane)
// ---------------------------------------------------------------------------
__device__ __forceinline__ void demb_compute(float d, float* a) {
    float tt = d * 4.2f;
#pragma unroll
    for (int i = 0; i < 20; i++) {
        float diff = tt - (float)(i + 1);
        float p = diff + 1.0f, q = 1.0f - diff;
        float s1 = (p > 0.0f) ? __expf(-1.0f / p) : 0.0f;
        float s2 = (q > 0.0f) ? __expf(-1.0f / q) : 0.0f;
        a[i] = DEMBC * s1 * s2;
    }
}

// ---------------------------------------------------------------------------
// message kernel (cooperative): 32 edges / block, 4 warps split k
// ---------------------------------------------------------------------------
__global__ void __launch_bounds__(TB) k_msg(
    const float* __restrict__ pos,
    const int* __restrict__ srcI, const int* __restrict__ dstI,
    const float* __restrict__ eattr, int E, int B,
    const float* __restrict__ W0, const float* __restrict__ W1)
{
    __shared__ float shH[64 * EPB];
    __shared__ float shN[NF * EPB];
    __shared__ float shA[NF * EPB];
    __shared__ float shR[3 * EPB];
    __shared__ int   shSi[EPB];
    __shared__ int   shDi[EPB];

    int tid  = threadIdx.x;
    int lane = tid & 31;
    int warp = tid >> 5;
    int e0 = blockIdx.x * EPB;

    // zero output accumulator
#pragma unroll
    for (int i = tid; i < NF * EPB; i += TB) shA[i] = 0.0f;

    // phase 1: geometry (warp 0)
    if (tid < EPB) {
        int e = min(e0 + tid, E - 1);
        int si = srcI[e], di = dstI[e];
        shSi[tid] = si; shDi[tid] = di;
        float vx = pos[di * 3 + 0] - pos[si * 3 + 0];
        float vy = pos[di * 3 + 1] - pos[si * 3 + 1];
        float vz = pos[di * 3 + 2] - pos[si * 3 + 2];
        float rn = rsqrtf(vx * vx + vy * vy + vz * vz);
        shR[tid]            = vx * rn;
        shR[EPB + tid]      = vy * rn;
        shR[2 * EPB + tid]  = vz * rn;
    }
    __syncthreads();

    // phase 2a: preload source-node feature rows into smem [f][e]
    for (int i = tid; i < NF * EPB; i += TB) {
        int e = i / NF, f = i - e * NF;
        shN[f * EPB + e] = g_node[shSi[e] * NF + f];
    }

    // phase 2b: hidden layer h (each warp computes its 16 k's for all lanes)
    {
        int ec = min(e0 + lane, E - 1);
        float inv = rsqrtf((float)B);
        float a[8];
#pragma unroll
        for (int b = 0; b < 8; b++) a[b] = (b < B) ? eattr[ec * B + b] : 0.0f;
        int kb = warp * KC;
#pragma unroll 4
        for (int j = 0; j < KC; j++) {
            float s = 0.0f;
#pragma unroll
            for (int b = 0; b < 8; b++)
                if (b < B) s += a[b] * W0[b * 64 + kb + j];
            shH[(kb + j) * EPB + lane] = siluN(s * inv) * 0.125f;
        }
    }
    __syncthreads();

    // phase 3: fold this warp's k-chunk through the TP
    float os[16], ov[24];
    tp_fold(shH, lane, warp * KC, shN,
            shR[lane], shR[EPB + lane], shR[2 * EPB + lane], W1, os, ov);

    // phase 4: reduce partials in smem
#pragma unroll
    for (int t = 0; t < 16; t++) atomicAdd(&shA[t * EPB + lane], os[t]);
#pragma unroll
    for (int t = 0; t < 24; t++) atomicAdd(&shA[(16 + t) * EPB + lane], ov[t]);
    __syncthreads();

    // phase 5: scatter to destination nodes
    for (int i = tid; i < NF * EPB; i += TB) {
        int e = i / NF, f = i - e * NF;
        if (e0 + e < E)
            atomicAdd(&g_msgs[shDi[e] * NF + f], shA[f * EPB + e]);
    }
}

// ---------------------------------------------------------------------------
// ligand embedding (cooperative): lig_emb[e] = tp(node[lig], sh(vec), mlp(demb))
// ---------------------------------------------------------------------------
__global__ void __launch_bounds__(TB) k_lig(
    const float* __restrict__ pos,
    const int* __restrict__ recI, const int* __restrict__ ligI, int EI,
    const float* __restrict__ W0, const float* __restrict__ W1)
{
    __shared__ float shH[64 * EPB];
    __shared__ float shN[NF * EPB];
    __shared__ float shA[NF * EPB];
    __shared__ float shB[20 * EPB];
    __shared__ float shR[3 * EPB];
    __shared__ int   shLi[EPB];

    int tid  = threadIdx.x;
    int lane = tid & 31;
    int warp = tid >> 5;
    int e0 = blockIdx.x * EPB;

#pragma unroll
    for (int i = tid; i < NF * EPB; i += TB) shA[i] = 0.0f;

    if (tid < EPB) {
        int e = min(e0 + tid, EI - 1);
        int ri = recI[e], li = ligI[e];
        shLi[tid] = li;
        float vx = pos[li * 3 + 0] - pos[ri * 3 + 0];
        float vy = pos[li * 3 + 1] - pos[ri * 3 + 1];
        float vz = pos[li * 3 + 2] - pos[ri * 3 + 2];
        float d2 = vx * vx + vy * vy + vz * vz;
        float invd = rsqrtf(d2);
        shR[tid]           = vx * invd;
        shR[EPB + tid]     = vy * invd;
        shR[2 * EPB + tid] = vz * invd;
        float a[20];
        demb_compute(d2 * invd, a);
#pragma unroll
        for (int i = 0; i < 20; i++) shB[i * EPB + tid] = a[i];
    }
    __syncthreads();

    for (int i = tid; i < NF * EPB; i += TB) {
        int e = i / NF, f = i - e * NF;
        shN[f * EPB + e] = g_node[shLi[e] * NF + f];
    }

    {
        float a[20];
#pragma unroll
        for (int i = 0; i < 20; i++) a[i] = shB[i * EPB + lane];
        int kb = warp * KC;
#pragma unroll 4
        for (int j = 0; j < KC; j++) {
            float s = 0.0f;
#pragma unroll
            for (int i = 0; i < 20; i++) s += a[i] * W0[i * 64 + kb + j];
            shH[(kb + j) * EPB + lane] = siluN(s) * 0.125f;
        }
    }
    __syncthreads();

    float os[16], ov[24];
    tp_fold(shH, lane, warp * KC, shN,
            shR[lane], shR[EPB + lane], shR[2 * EPB + lane], W1, os, ov);

#pragma unroll
    for (int t = 0; t < 16; t++) atomicAdd(&shA[t * EPB + lane], os[t]);
#pragma unroll
    for (int t = 0; t < 24; t++) atomicAdd(&shA[(16 + t) * EPB + lane], ov[t]);
    __syncthreads();

    for (int i = tid; i < NF * EPB; i += TB) {
        int e = i / NF, f = i - e * NF;
        if (e0 + e < EI)
            g_lig[(e0 + e) * NF + f] = shA[f * EPB + e];
    }
}

// ---------------------------------------------------------------------------
// receptor TP readout (cooperative): out[e][o], o<8
// ---------------------------------------------------------------------------
__global__ void __launch_bounds__(TB) k_rec(
    const float* __restrict__ pos,
    const int* __restrict__ recI, const int* __restrict__ ligI, int EI,
    const float* __restrict__ W0, const float* __restrict__ W1,
    float* __restrict__ out)
{
    __shared__ float shH[64 * EPB];
    __shared__ float shL[NF * EPB];
    __shared__ float shRn[NF * EPB];
    __shared__ float shB[20 * EPB];
    __shared__ float shA[8 * EPB];
    __shared__ int   shRi[EPB];

    int tid  = threadIdx.x;
    int lane = tid & 31;
    int warp = tid >> 5;
    int e0 = blockIdx.x * EPB;

#pragma unroll
    for (int i = tid; i < 8 * EPB; i += TB) shA[i] = 0.0f;

    if (tid < EPB) {
        int e = min(e0 + tid, EI - 1);
        int ri = recI[e], li = ligI[e];
        shRi[tid] = ri;
        float vx = pos[li * 3 + 0] - pos[ri * 3 + 0];
        float vy = pos[li * 3 + 1] - pos[ri * 3 + 1];
        float vz = pos[li * 3 + 2] - pos[ri * 3 + 2];
        float d2 = vx * vx + vy * vy + vz * vz;
        float a[20];
        demb_compute(d2 * rsqrtf(d2), a);
#pragma unroll
        for (int i = 0; i < 20; i++) shB[i * EPB + tid] = a[i];
    }
    __syncthreads();

    for (int i = tid; i < NF * EPB; i += TB) {
        int e = i / NF, f = i - e * NF;
        int ec = min(e0 + e, EI - 1);
        shL[f * EPB + e]  = g_lig[ec * NF + f];
        shRn[f * EPB + e] = g_node[shRi[e] * NF + f];
    }

    {
        float a[20];
#pragma unroll
        for (int i = 0; i < 20; i++) a[i] = shB[i * EPB + lane];
        int kb = warp * KC;
#pragma unroll 4
        for (int j = 0; j < KC; j++) {
            float s = 0.0f;
#pragma unroll
            for (int i = 0; i < 20; i++) s += a[i] * W0[i * 64 + kb + j];
            shH[(kb + j) * EPB + lane] = siluN(s) * 0.125f;
        }
    }
    __syncthreads();

    // fold this warp's k-chunk of the 2560-wide weight GEMV through the TP
    float acc[8];
#pragma unroll
    for (int t = 0; t < 8; t++) acc[t] = 0.0f;
    const float* hp = shH + warp * KC * EPB + lane;
    const float* Wk = W1 + warp * KC * 2560;

    // scalar x scalar -> 8x0e : w1[u][v][o] at (u*16+v)*8
#pragma unroll 1
    for (int u = 0; u < 16; u++) {
        float lu = shL[u * EPB + lane];
#pragma unroll 1
        for (int v = 0; v < 16; v++) {
            float w8[8];
#pragma unroll
            for (int t = 0; t < 8; t++) w8[t] = 0.0f;
            const float* base = Wk + (u * 16 + v) * 8;
#pragma unroll 4
            for (int j = 0; j < KC; j++) {
                float hk = hp[j * EPB];
                const float4* p = reinterpret_cast<const float4*>(base + j * 2560);
                float4 q0 = __ldg(p), q1 = __ldg(p + 1);
                w8[0] += hk * q0.x; w8[1] += hk * q0.y; w8[2] += hk * q0.z; w8[3] += hk * q0.w;
                w8[4] += hk * q1.x; w8[5] += hk * q1.y; w8[6] += hk * q1.z; w8[7] += hk * q1.w;
            }
            float cf = lu * shRn[v * EPB + lane];
#pragma unroll
            for (int t = 0; t < 8; t++) acc[t] += cf * w8[t];
        }
    }

    // vector x vector -> 8x0e : w2[u][v][o] at 2048 + (u*8+v)*8, coef (lv.rv)/sqrt3
#pragma unroll 1
    for (int u = 0; u < 8; u++) {
        float l0 = shL[(16 + u * 3) * EPB + lane];
        float l1 = shL[(17 + u * 3) * EPB + lane];
        float l2 = shL[(18 + u * 3) * EPB + lane];
#pragma unroll 1
        for (int v = 0; v < 8; v++) {
            float w8[8];
#pragma unroll
            for (int t = 0; t < 8; t++) w8[t] = 0.0f;
            const float* base = Wk + 2048 + (u * 8 + v) * 8;
#pragma unroll 4
            for (int j = 0; j < KC; j++) {
                float hk = hp[j * EPB];
                const float4* p = reinterpret_cast<const float4*>(base + j * 2560);
                float4 q0 = __ldg(p), q1 = __ldg(p + 1);
                w8[0] += hk * q0.x; w8[1] += hk * q0.y; w8[2] += hk * q0.z; w8[3] += hk * q0.w;
                w8[4] += hk * q1.x; w8[5] += hk * q1.y; w8[6] += hk * q1.z; w8[7] += hk * q1.w;
            }
            float cf = (l0 * shRn[(16 + v * 3) * EPB + lane] +
                        l1 * shRn[(17 + v * 3) * EPB + lane] +
                        l2 * shRn[(18 + v * 3) * EPB + lane]) * INVS3;
#pragma unroll
            for (int t = 0; t < 8; t++) acc[t] += cf * w8[t];
        }
    }

#pragma unroll
    for (int t = 0; t < 8; t++) atomicAdd(&shA[t * EPB + lane], acc[t]);
    __syncthreads();

    for (int i = tid; i < 8 * EPB; i += TB) {
        int e = i / 8, o = i - e * 8;
        if (e0 + e < EI)
            out[(e0 + e) * 8 + o] = PWREC * shA[o * EPB + e];
    }
}

// ---------------------------------------------------------------------------
// host launcher (graph-capturable: kernel launches only)
// ---------------------------------------------------------------------------
extern "C" void kernel_launch(void* const* d_in, const int* in_sizes, int n_in,
                              void* d_out, int out_size) {
    (void)n_in; (void)out_size;
    const float* x       = (const float*)d_in[0];
    const float* pos     = (const float*)d_in[1];
    const int*   eidx    = (const int*)  d_in[2];
    const float* eattr   = (const float*)d_in[3];
    const int*   iidx    = (const int*)  d_in[4];
    const float* emb_w0  = (const float*)d_in[5];
    const float* emb_w1  = (const float*)d_in[6];
    const float* imp0    = (const float*)d_in[7];
    const float* msg0_w0 = (const float*)d_in[8];
    const float* msg0_w1 = (const float*)d_in[9];
    const float* upd0_w0 = (const float*)d_in[10];
    const float* upd0_w1 = (const float*)d_in[11];
    const float* imp1    = (const float*)d_in[12];
    const float* msg1_w0 = (const float*)d_in[13];
    const float* msg1_w1 = (const float*)d_in[14];
    const float* upd1_w0 = (const float*)d_in[15];
    const float* upd1_w1 = (const float*)d_in[16];
    const float* lig_w0  = (const float*)d_in[17];
    const float* lig_w1  = (const float*)d_in[18];
    const float* rec_w0  = (const float*)d_in[19];
    const float* rec_w1  = (const float*)d_in[20];

    int N  = in_sizes[1] / 3;
    int A  = in_sizes[0] / N;
    int E  = in_sizes[2] / 2;
    int B  = in_sizes[3] / E;
    int EI = in_sizes[4] / 2;
    const int* src  = eidx;
    const int* dst  = eidx + E;
    const int* recI = iidx;
    const int* ligI = iidx + EI;
    float degf = (float)E / (float)N;

    int gn = (N + TB - 1) / TB;
    int ge = (E + EPB - 1) / EPB;
    int gi = (EI + EPB - 1) / EPB;
    int gz = (N * NF + 255) / 256;

    k_embed<<<gn, TB>>>(x, N, A, emb_w0, emb_w1);

    // message-passing step 0
    k_zero_msgs<<<gz, 256>>>(N * NF);
    k_msg<<<ge, TB>>>(pos, src, dst, eattr, E, B, msg0_w0, msg0_w1);
    k_update<<<gn, TB>>>(N, imp0, degf, upd0_w0, upd0_w1, 1.0f);

    // message-passing step 1
    k_zero_msgs<<<gz, 256>>>(N * NF);
    k_msg<<<ge, TB>>>(pos, src, dst, eattr, E, B, msg1_w0, msg1_w1);
    k_update<<<gn, TB>>>(N, imp1, degf, upd1_w0, upd1_w1, 0.5f);

    // readout
    k_lig<<<gi, TB>>>(pos, recI, ligI, EI, lig_w0, lig_w1);
    k_rec<<<gi, TB>>>(pos, recI, ligI, EI, rec_w0, rec_w1, (float*)d_out);
}

// round 6
// speedup vs baseline: 2.1799x; 1.6839x over previous
#include <cuda_runtime.h>
#include <math.h>

// ---------------------------------------------------------------------------
// InteractionPredictor: e3nn-style equivariant GNN, fully fused fp32.
// node irreps: 16x0e + 8x1o (40 floats). Two message-passing steps, then a
// ligand/receptor tensor-product readout -> [EI, 8].
//
// R5: 64 edges / 256-thread block. 8 warps each own a k-chunk of 8 hidden
// units, computed directly into registers (no smem h). Each lane carries TWO
// edges (lane, lane+32) so every warp-uniform weight float4 feeds 8 FMAs.
// Fold split into scalar phase (A+B) and vector phase (C+D) to cap register
// pressure. Per-warp partials reduce via shared-memory atomics.
// ---------------------------------------------------------------------------

#define TBE    256         /* threads per edge block     */
#define EPB    64          /* edges per block            */
#define KC     8           /* k-chunk per warp (8 warps) */
#define NF     40
#define NMAX   16384
#define EIMAX  65536

__device__ float g_node[NMAX * NF];
__device__ float g_msgs[NMAX * NF];
__device__ float g_lig [EIMAX * NF];

#define C24    0.20412414523193154f   /* sqrt(1/24)  path weight (both irreps) */
#define C24S3  0.35355339059327373f   /* sqrt(3)/sqrt(24) = sqrt(1/8)          */
#define INVS3  0.57735026918962576f   /* 1/sqrt(3)                              */
#define PWREC  0.05590169943749474f   /* 1/sqrt(320)                            */
#define DEMBC  8.4335731f             /* 1.14136 * e^2 (sqrt(20) folds into MLP)*/
#define INV32  0.17677669529663687f   /* 1/sqrt(32)                             */

__device__ __forceinline__ float siluN(float x) {
    return x * (1.0f / (1.0f + __expf(-x))) * 1.6789717f;
}

// ---------------------------------------------------------------------------
// node embedding; also zeroes the message accumulator for step 0
// ---------------------------------------------------------------------------
__global__ void k_embed(const float* __restrict__ x, int N, int A,
                        const float* __restrict__ W0, const float* __restrict__ W1) {
    int n = blockIdx.x * blockDim.x + threadIdx.x;
    if (n >= N) return;
    float inv = rsqrtf((float)A);
    float a[16];
#pragma unroll
    for (int b = 0; b < 16; b++) a[b] = (b < A) ? x[n * A + b] : 0.0f;
    float h[64];
#pragma unroll 4
    for (int k = 0; k < 64; k++) {
        float s = 0.0f;
#pragma unroll
        for (int b = 0; b < 16; b++)
            if (b < A) s += a[b] * W0[b * 64 + k];
        h[k] = siluN(s * inv) * 0.125f;
    }
    float* nr = g_node + n * NF;
#pragma unroll
    for (int w = 0; w < 16; w++) {
        float s = 0.0f;
#pragma unroll 8
        for (int k = 0; k < 64; k++) s += h[k] * W1[k * 16 + w];
        nr[w] = s;
    }
#pragma unroll
    for (int t = 0; t < 24; t++) nr[16 + t] = 0.0f;
    float* mr = g_msgs + n * NF;
#pragma unroll
    for (int t = 0; t < NF; t++) mr[t] = 0.0f;
}

// ---------------------------------------------------------------------------
// node update; re-zeroes this node's message row after consuming it
// ---------------------------------------------------------------------------
__global__ void k_update(int N, const float* __restrict__ imp, float degf,
                         const float* __restrict__ W0, const float* __restrict__ W1,
                         float gmul) {
    int n = blockIdx.x * blockDim.x + threadIdx.x;
    if (n >= N) return;
    float scale = imp[0] * rsqrtf(degf);
    float* nr = g_node + n * NF;
    float* mr = g_msgs + n * NF;
    float a[32];
#pragma unroll
    for (int t = 0; t < 16; t++) a[t] = mr[t] * scale;
#pragma unroll
    for (int t = 0; t < 16; t++) a[16 + t] = nr[t];
    float ge[24];
#pragma unroll
    for (int t = 0; t < 24; t++) ge[t] = (mr[16 + t] * scale + nr[16 + t]) * gmul;
#pragma unroll
    for (int t = 0; t < NF; t++) mr[t] = 0.0f;   // ready for next step
    float h[64];
#pragma unroll 2
    for (int k = 0; k < 64; k++) {
        float s = 0.0f;
#pragma unroll
        for (int b = 0; b < 32; b++) s += a[b] * W0[b * 64 + k];
        h[k] = siluN(s * INV32) * 0.125f;
    }
    float sc[16];
#pragma unroll
    for (int w = 0; w < 16; w++) {
        float s = 0.0f;
#pragma unroll 8
        for (int k = 0; k < 64; k++) s += h[k] * W1[k * 16 + w];
        sc[w] = s;
    }
#pragma unroll
    for (int w = 0; w < 16; w++) nr[w] = sc[w];
#pragma unroll
    for (int t = 0; t < 24; t++) nr[16 + t] = ge[t];
}

// ---------------------------------------------------------------------------
// distance embedding (per lane)
// ---------------------------------------------------------------------------
__device__ __forceinline__ void demb_compute(float d, float* a) {
    float tt = d * 4.2f;
#pragma unroll
    for (int i = 0; i < 20; i++) {
        float diff = tt - (float)(i + 1);
        float p = diff + 1.0f, q = 1.0f - diff;
        float s1 = (p > 0.0f) ? __expf(-1.0f / p) : 0.0f;
        float s2 = (q > 0.0f) ? __expf(-1.0f / q) : 0.0f;
        a[i] = DEMBC * s1 * s2;
    }
}

// ---------------------------------------------------------------------------
// Two-edge TP fold for one k-chunk (KC hidden units, in registers).
// shN: node feats [40][EPB], shR: unit vec [3][EPB], shA: accum [40][EPB].
// W1k points at this warp's rows of W1 ([64, 576] row-major).
// ---------------------------------------------------------------------------
__device__ __forceinline__ void tp_fold2(
    const float* __restrict__ ha, const float* __restrict__ hb, int lane,
    const float* __restrict__ shN, const float* __restrict__ shR,
    const float* __restrict__ W1k,
    float* __restrict__ shA)
{
    float ra0 = shR[lane],      ra1 = shR[EPB + lane],      ra2 = shR[2 * EPB + lane];
    float rb0 = shR[lane + 32], rb1 = shR[EPB + lane + 32], rb2 = shR[2 * EPB + lane + 32];

    // -------- scalar-output phase: blocks A and B -> os --------
    {
        float osA[16], osB[16];
#pragma unroll
        for (int t = 0; t < 16; t++) { osA[t] = 0.0f; osB[t] = 0.0f; }

        // Block A: 0e x 0e -> 0e ; cols [u*16, +16), u<16
#pragma unroll 1
        for (int u = 0; u < 16; u++) {
            float wa[16], wb[16];
#pragma unroll
            for (int t = 0; t < 16; t++) { wa[t] = 0.0f; wb[t] = 0.0f; }
            const float* base = W1k + u * 16;
#pragma unroll
            for (int j = 0; j < KC; j++) {
                const float4* p = reinterpret_cast<const float4*>(base + j * 576);
                float4 q0 = __ldg(p), q1 = __ldg(p + 1), q2 = __ldg(p + 2), q3 = __ldg(p + 3);
                float A = ha[j], Bv = hb[j];
                wa[0]+=A*q0.x; wa[1]+=A*q0.y; wa[2]+=A*q0.z; wa[3]+=A*q0.w;
                wa[4]+=A*q1.x; wa[5]+=A*q1.y; wa[6]+=A*q1.z; wa[7]+=A*q1.w;
                wa[8]+=A*q2.x; wa[9]+=A*q2.y; wa[10]+=A*q2.z; wa[11]+=A*q2.w;
                wa[12]+=A*q3.x; wa[13]+=A*q3.y; wa[14]+=A*q3.z; wa[15]+=A*q3.w;
                wb[0]+=Bv*q0.x; wb[1]+=Bv*q0.y; wb[2]+=Bv*q0.z; wb[3]+=Bv*q0.w;
                wb[4]+=Bv*q1.x; wb[5]+=Bv*q1.y; wb[6]+=Bv*q1.z; wb[7]+=Bv*q1.w;
                wb[8]+=Bv*q2.x; wb[9]+=Bv*q2.y; wb[10]+=Bv*q2.z; wb[11]+=Bv*q2.w;
                wb[12]+=Bv*q3.x; wb[13]+=Bv*q3.y; wb[14]+=Bv*q3.z; wb[15]+=Bv*q3.w;
            }
            float cfa = C24 * shN[u * EPB + lane];
            float cfb = C24 * shN[u * EPB + lane + 32];
#pragma unroll
            for (int t = 0; t < 16; t++) { osA[t] += cfa * wa[t]; osB[t] += cfb * wb[t]; }
        }

        // Block B: 1o x 1o -> 0e ; cols [256+u*16), u<8 ; coef C24*(xv_u . r)
#pragma unroll 1
        for (int u = 0; u < 8; u++) {
            float wa[16], wb[16];
#pragma unroll
            for (int t = 0; t < 16; t++) { wa[t] = 0.0f; wb[t] = 0.0f; }
            const float* base = W1k + 256 + u * 16;
#pragma unroll
            for (int j = 0; j < KC; j++) {
                const float4* p = reinterpret_cast<const float4*>(base + j * 576);
                float4 q0 = __ldg(p), q1 = __ldg(p + 1), q2 = __ldg(p + 2), q3 = __ldg(p + 3);
                float A = ha[j], Bv = hb[j];
                wa[0]+=A*q0.x; wa[1]+=A*q0.y; wa[2]+=A*q0.z; wa[3]+=A*q0.w;
                wa[4]+=A*q1.x; wa[5]+=A*q1.y; wa[6]+=A*q1.z; wa[7]+=A*q1.w;
                wa[8]+=A*q2.x; wa[9]+=A*q2.y; wa[10]+=A*q2.z; wa[11]+=A*q2.w;
                wa[12]+=A*q3.x; wa[13]+=A*q3.y; wa[14]+=A*q3.z; wa[15]+=A*q3.w;
                wb[0]+=Bv*q0.x; wb[1]+=Bv*q0.y; wb[2]+=Bv*q0.z; wb[3]+=Bv*q0.w;
                wb[4]+=Bv*q1.x; wb[5]+=Bv*q1.y; wb[6]+=Bv*q1.z; wb[7]+=Bv*q1.w;
                wb[8]+=Bv*q2.x; wb[9]+=Bv*q2.y; wb[10]+=Bv*q2.z; wb[11]+=Bv*q2.w;
                wb[12]+=Bv*q3.x; wb[13]+=Bv*q3.y; wb[14]+=Bv*q3.z; wb[15]+=Bv*q3.w;
            }
            float cfa = C24 * (shN[(16 + u * 3) * EPB + lane] * ra0 +
                               shN[(17 + u * 3) * EPB + lane] * ra1 +
                               shN[(18 + u * 3) * EPB + lane] * ra2);
            float cfb = C24 * (shN[(16 + u * 3) * EPB + lane + 32] * rb0 +
                               shN[(17 + u * 3) * EPB + lane + 32] * rb1 +
                               shN[(18 + u * 3) * EPB + lane + 32] * rb2);
#pragma unroll
            for (int t = 0; t < 16; t++) { osA[t] += cfa * wa[t]; osB[t] += cfb * wb[t]; }
        }

#pragma unroll
        for (int t = 0; t < 16; t++) {
            atomicAdd(&shA[t * EPB + lane],      osA[t]);
            atomicAdd(&shA[t * EPB + lane + 32], osB[t]);
        }
    }

    // -------- vector-output phase: blocks C and D -> ov --------
    {
        float ovA[24], ovB[24];
#pragma unroll
        for (int t = 0; t < 24; t++) { ovA[t] = 0.0f; ovB[t] = 0.0f; }

        // Block C: 0e x 1o -> 1o ; cols [384+u*8), u<16
#pragma unroll 1
        for (int u = 0; u < 16; u++) {
            float wa[8], wb[8];
#pragma unroll
            for (int t = 0; t < 8; t++) { wa[t] = 0.0f; wb[t] = 0.0f; }
            const float* base = W1k + 384 + u * 8;
#pragma unroll
            for (int j = 0; j < KC; j++) {
                const float4* p = reinterpret_cast<const float4*>(base + j * 576);
                float4 q0 = __ldg(p), q1 = __ldg(p + 1);
                float A = ha[j], Bv = hb[j];
                wa[0]+=A*q0.x; wa[1]+=A*q0.y; wa[2]+=A*q0.z; wa[3]+=A*q0.w;
                wa[4]+=A*q1.x; wa[5]+=A*q1.y; wa[6]+=A*q1.z; wa[7]+=A*q1.w;
                wb[0]+=Bv*q0.x; wb[1]+=Bv*q0.y; wb[2]+=Bv*q0.z; wb[3]+=Bv*q0.w;
                wb[4]+=Bv*q1.x; wb[5]+=Bv*q1.y; wb[6]+=Bv*q1.z; wb[7]+=Bv*q1.w;
            }
            float cfa = C24S3 * shN[u * EPB + lane];
            float cfb = C24S3 * shN[u * EPB + lane + 32];
#pragma unroll
            for (int t = 0; t < 8; t++) {
                float sa = cfa * wa[t], sb = cfb * wb[t];
                ovA[t*3+0] += sa * ra0; ovA[t*3+1] += sa * ra1; ovA[t*3+2] += sa * ra2;
                ovB[t*3+0] += sb * rb0; ovB[t*3+1] += sb * rb1; ovB[t*3+2] += sb * rb2;
            }
        }

        // Block D: 1o x 0e -> 1o ; cols [512+u*8), u<8
#pragma unroll 1
        for (int u = 0; u < 8; u++) {
            float wa[8], wb[8];
#pragma unroll
            for (int t = 0; t < 8; t++) { wa[t] = 0.0f; wb[t] = 0.0f; }
            const float* base = W1k + 512 + u * 8;
#pragma unroll
            for (int j = 0; j < KC; j++) {
                const float4* p = reinterpret_cast<const float4*>(base + j * 576);
                float4 q0 = __ldg(p), q1 = __ldg(p + 1);
                float A = ha[j], Bv = hb[j];
                wa[0]+=A*q0.x; wa[1]+=A*q0.y; wa[2]+=A*q0.z; wa[3]+=A*q0.w;
                wa[4]+=A*q1.x; wa[5]+=A*q1.y; wa[6]+=A*q1.z; wa[7]+=A*q1.w;
                wb[0]+=Bv*q0.x; wb[1]+=Bv*q0.y; wb[2]+=Bv*q0.z; wb[3]+=Bv*q0.w;
                wb[4]+=Bv*q1.x; wb[5]+=Bv*q1.y; wb[6]+=Bv*q1.z; wb[7]+=Bv*q1.w;
            }
            float ca0 = C24 * shN[(16 + u * 3) * EPB + lane];
            float ca1 = C24 * shN[(17 + u * 3) * EPB + lane];
            float ca2 = C24 * shN[(18 + u * 3) * EPB + lane];
            float cb0 = C24 * shN[(16 + u * 3) * EPB + lane + 32];
            float cb1 = C24 * shN[(17 + u * 3) * EPB + lane + 32];
            float cb2 = C24 * shN[(18 + u * 3) * EPB + lane + 32];
#pragma unroll
            for (int t = 0; t < 8; t++) {
                ovA[t*3+0] += ca0 * wa[t]; ovA[t*3+1] += ca1 * wa[t]; ovA[t*3+2] += ca2 * wa[t];
                ovB[t*3+0] += cb0 * wb[t]; ovB[t*3+1] += cb1 * wb[t]; ovB[t*3+2] += cb2 * wb[t];
            }
        }

#pragma unroll
        for (int t = 0; t < 24; t++) {
            atomicAdd(&shA[(16 + t) * EPB + lane],      ovA[t]);
            atomicAdd(&shA[(16 + t) * EPB + lane + 32], ovB[t]);
        }
    }
}

// ---------------------------------------------------------------------------
// message kernel: 64 edges / block, 8 warps split k (8 each), 2 edges / lane
// ---------------------------------------------------------------------------
__global__ void __launch_bounds__(TBE) k_msg(
    const float* __restrict__ pos,
    const int* __restrict__ srcI, const int* __restrict__ dstI,
    const float* __restrict__ eattr, int E, int B,
    const float* __restrict__ W0, const float* __restrict__ W1)
{
    __shared__ float shN[NF * EPB];
    __shared__ float shA[NF * EPB];
    __shared__ float shR[3 * EPB];
    __shared__ int   shSi[EPB];
    __shared__ int   shDi[EPB];

    int tid  = threadIdx.x;
    int lane = tid & 31;
    int warp = tid >> 5;
    int e0 = blockIdx.x * EPB;

    for (int i = tid; i < NF * EPB; i += TBE) shA[i] = 0.0f;

    if (tid < EPB) {
        int e = min(e0 + tid, E - 1);
        int si = srcI[e], di = dstI[e];
        shSi[tid] = si; shDi[tid] = di;
        float vx = pos[di * 3 + 0] - pos[si * 3 + 0];
        float vy = pos[di * 3 + 1] - pos[si * 3 + 1];
        float vz = pos[di * 3 + 2] - pos[si * 3 + 2];
        float rn = rsqrtf(vx * vx + vy * vy + vz * vz);
        shR[tid]           = vx * rn;
        shR[EPB + tid]     = vy * rn;
        shR[2 * EPB + tid] = vz * rn;
    }
    __syncthreads();

    // preload source-node features [f][e]
    for (int i = tid; i < NF * EPB; i += TBE) {
        int e = i & (EPB - 1), f = i >> 6;
        shN[f * EPB + e] = g_node[shSi[e] * NF + f];
    }

    // this warp's k-chunk of h, in registers, for both edges
    float ha[KC], hb[KC];
    {
        float inv = rsqrtf((float)B);
        int kb = warp * KC;
        int ea = min(e0 + lane, E - 1);
        int eb = min(e0 + lane + 32, E - 1);
        float aa[8], ab[8];
#pragma unroll
        for (int b = 0; b < 8; b++) {
            aa[b] = (b < B) ? eattr[ea * B + b] : 0.0f;
            ab[b] = (b < B) ? eattr[eb * B + b] : 0.0f;
        }
#pragma unroll
        for (int j = 0; j < KC; j++) {
            float sa = 0.0f, sb = 0.0f;
#pragma unroll
            for (int b = 0; b < 8; b++)
                if (b < B) {
                    float w = W0[b * 64 + kb + j];
                    sa += aa[b] * w; sb += ab[b] * w;
                }
            ha[j] = siluN(sa * inv) * 0.125f;
            hb[j] = siluN(sb * inv) * 0.125f;
        }
    }
    __syncthreads();

    tp_fold2(ha, hb, lane, shN, shR, W1 + warp * KC * 576, shA);
    __syncthreads();

    // scatter to destination nodes
    for (int i = tid; i < NF * EPB; i += TBE) {
        int e = i & (EPB - 1), f = i >> 6;
        if (e0 + e < E)
            atomicAdd(&g_msgs[shDi[e] * NF + f], shA[f * EPB + e]);
    }
}

// ---------------------------------------------------------------------------
// ligand embedding
// ---------------------------------------------------------------------------
__global__ void __launch_bounds__(TBE) k_lig(
    const float* __restrict__ pos,
    const int* __restrict__ recI, const int* __restrict__ ligI, int EI,
    const float* __restrict__ W0, const float* __restrict__ W1)
{
    __shared__ float shN[NF * EPB];
    __shared__ float shA[NF * EPB];
    __shared__ float shB[20 * EPB];
    __shared__ float shR[3 * EPB];
    __shared__ int   shLi[EPB];

    int tid  = threadIdx.x;
    int lane = tid & 31;
    int warp = tid >> 5;
    int e0 = blockIdx.x * EPB;

    for (int i = tid; i < NF * EPB; i += TBE) shA[i] = 0.0f;

    if (tid < EPB) {
        int e = min(e0 + tid, EI - 1);
        int ri = recI[e], li = ligI[e];
        shLi[tid] = li;
        float vx = pos[li * 3 + 0] - pos[ri * 3 + 0];
        float vy = pos[li * 3 + 1] - pos[ri * 3 + 1];
        float vz = pos[li * 3 + 2] - pos[ri * 3 + 2];
        float d2 = vx * vx + vy * vy + vz * vz;
        float invd = rsqrtf(d2);
        shR[tid]           = vx * invd;
        shR[EPB + tid]     = vy * invd;
        shR[2 * EPB + tid] = vz * invd;
        float a[20];
        demb_compute(d2 * invd, a);
#pragma unroll
        for (int i = 0; i < 20; i++) shB[i * EPB + tid] = a[i];
    }
    __syncthreads();

    for (int i = tid; i < NF * EPB; i += TBE) {
        int e = i & (EPB - 1), f = i >> 6;
        shN[f * EPB + e] = g_node[shLi[e] * NF + f];
    }

    float ha[KC], hb[KC];
    {
        int kb = warp * KC;
        float aa[20], ab[20];
#pragma unroll
        for (int i = 0; i < 20; i++) {
            aa[i] = shB[i * EPB + lane];
            ab[i] = shB[i * EPB + lane + 32];
        }
#pragma unroll
        for (int j = 0; j < KC; j++) {
            float sa = 0.0f, sb = 0.0f;
#pragma unroll
            for (int i = 0; i < 20; i++) {
                float w = W0[i * 64 + kb + j];
                sa += aa[i] * w; sb += ab[i] * w;
            }
            ha[j] = siluN(sa) * 0.125f;
            hb[j] = siluN(sb) * 0.125f;
        }
    }
    __syncthreads();

    tp_fold2(ha, hb, lane, shN, shR, W1 + warp * KC * 576, shA);
    __syncthreads();

    for (int i = tid; i < NF * EPB; i += TBE) {
        int e = i & (EPB - 1), f = i >> 6;
        if (e0 + e < EI)
            g_lig[(e0 + e) * NF + f] = shA[f * EPB + e];
    }
}

// ---------------------------------------------------------------------------
// receptor TP readout: out[e][o], o<8
// ---------------------------------------------------------------------------
__global__ void __launch_bounds__(TBE) k_rec(
    const float* __restrict__ pos,
    const int* __restrict__ recI, const int* __restrict__ ligI, int EI,
    const float* __restrict__ W0, const float* __restrict__ W1,
    float* __restrict__ out)
{
    __shared__ float shL [NF * EPB];
    __shared__ float shRn[NF * EPB];
    __shared__ float shB [20 * EPB];
    __shared__ float shA [8 * EPB];
    __shared__ int   shRi[EPB];

    int tid  = threadIdx.x;
    int lane = tid & 31;
    int warp = tid >> 5;
    int e0 = blockIdx.x * EPB;

    for (int i = tid; i < 8 * EPB; i += TBE) shA[i] = 0.0f;

    if (tid < EPB) {
        int e = min(e0 + tid, EI - 1);
        int ri = recI[e], li = ligI[e];
        shRi[tid] = ri;
        float vx = pos[li * 3 + 0] - pos[ri * 3 + 0];
        float vy = pos[li * 3 + 1] - pos[ri * 3 + 1];
        float vz = pos[li * 3 + 2] - pos[ri * 3 + 2];
        float d2 = vx * vx + vy * vy + vz * vz;
        float a[20];
        demb_compute(d2 * rsqrtf(d2), a);
#pragma unroll
        for (int i = 0; i < 20; i++) shB[i * EPB + tid] = a[i];
    }
    __syncthreads();

    for (int i = tid; i < NF * EPB; i += TBE) {
        int e = i & (EPB - 1), f = i >> 6;
        int ec = min(e0 + e, EI - 1);
        shL [f * EPB + e] = g_lig[ec * NF + f];
        shRn[f * EPB + e] = g_node[shRi[e] * NF + f];
    }

    float ha[KC], hb[KC];
    {
        int kb = warp * KC;
        float aa[20], ab[20];
#pragma unroll
        for (int i = 0; i < 20; i++) {
            aa[i] = shB[i * EPB + lane];
            ab[i] = shB[i * EPB + lane + 32];
        }
#pragma unroll
        for (int j = 0; j < KC; j++) {
            float sa = 0.0f, sb = 0.0f;
#pragma unroll
            for (int i = 0; i < 20; i++) {
                float w = W0[i * 64 + kb + j];
                sa += aa[i] * w; sb += ab[i] * w;
            }
            ha[j] = siluN(sa) * 0.125f;
            hb[j] = siluN(sb) * 0.125f;
        }
    }
    __syncthreads();

    float accA[8], accB[8];
#pragma unroll
    for (int t = 0; t < 8; t++) { accA[t] = 0.0f; accB[t] = 0.0f; }
    const float* Wk = W1 + warp * KC * 2560;

    // scalar x scalar -> 8x0e : w1[u][v][o] at (u*16+v)*8
#pragma unroll 1
    for (int u = 0; u < 16; u++) {
        float lua = shL[u * EPB + lane];
        float lub = shL[u * EPB + lane + 32];
#pragma unroll 1
        for (int v = 0; v < 16; v++) {
            float wa[8], wb[8];
#pragma unroll
            for (int t = 0; t < 8; t++) { wa[t] = 0.0f; wb[t] = 0.0f; }
            const float* base = Wk + (u * 16 + v) * 8;
#pragma unroll
            for (int j = 0; j < KC; j++) {
                const float4* p = reinterpret_cast<const float4*>(base + j * 2560);
                float4 q0 = __ldg(p), q1 = __ldg(p + 1);
                float A = ha[j], Bv = hb[j];
                wa[0]+=A*q0.x; wa[1]+=A*q0.y; wa[2]+=A*q0.z; wa[3]+=A*q0.w;
                wa[4]+=A*q1.x; wa[5]+=A*q1.y; wa[6]+=A*q1.z; wa[7]+=A*q1.w;
                wb[0]+=Bv*q0.x; wb[1]+=Bv*q0.y; wb[2]+=Bv*q0.z; wb[3]+=Bv*q0.w;
                wb[4]+=Bv*q1.x; wb[5]+=Bv*q1.y; wb[6]+=Bv*q1.z; wb[7]+=Bv*q1.w;
            }
            float cfa = lua * shRn[v * EPB + lane];
            float cfb = lub * shRn[v * EPB + lane + 32];
#pragma unroll
            for (int t = 0; t < 8; t++) { accA[t] += cfa * wa[t]; accB[t] += cfb * wb[t]; }
        }
    }

    // vector x vector -> 8x0e : w2[u][v][o] at 2048 + (u*8+v)*8, coef (lv.rv)/sqrt3
#pragma unroll 1
    for (int u = 0; u < 8; u++) {
        float la0 = shL[(16 + u * 3) * EPB + lane];
        float la1 = shL[(17 + u * 3) * EPB + lane];
        float la2 = shL[(18 + u * 3) * EPB + lane];
        float lb0 = shL[(16 + u * 3) * EPB + lane + 32];
        float lb1 = shL[(17 + u * 3) * EPB + lane + 32];
        float lb2 = shL[(18 + u * 3) * EPB + lane + 32];
#pragma unroll 1
        for (int v = 0; v < 8; v++) {
            float wa[8], wb[8];
#pragma unroll
            for (int t = 0; t < 8; t++) { wa[t] = 0.0f; wb[t] = 0.0f; }
            const float* base = Wk + 2048 + (u * 8 + v) * 8;
#pragma unroll
            for (int j = 0; j < KC; j++) {
                const float4* p = reinterpret_cast<const float4*>(base + j * 2560);
                float4 q0 = __ldg(p), q1 = __ldg(p + 1);
                float A = ha[j], Bv = hb[j];
                wa[0]+=A*q0.x; wa[1]+=A*q0.y; wa[2]+=A*q0.z; wa[3]+=A*q0.w;
                wa[4]+=A*q1.x; wa[5]+=A*q1.y; wa[6]+=A*q1.z; wa[7]+=A*q1.w;
                wb[0]+=Bv*q0.x; wb[1]+=Bv*q0.y; wb[2]+=Bv*q0.z; wb[3]+=Bv*q0.w;
                wb[4]+=Bv*q1.x; wb[5]+=Bv*q1.y; wb[6]+=Bv*q1.z; wb[7]+=Bv*q1.w;
            }
            float cfa = (la0 * shRn[(16 + v * 3) * EPB + lane] +
                         la1 * shRn[(17 + v * 3) * EPB + lane] +
                         la2 * shRn[(18 + v * 3) * EPB + lane]) * INVS3;
            float cfb = (lb0 * shRn[(16 + v * 3) * EPB + lane + 32] +
                         lb1 * shRn[(17 + v * 3) * EPB + lane + 32] +
                         lb2 * shRn[(18 + v * 3) * EPB + lane + 32]) * INVS3;
#pragma unroll
            for (int t = 0; t < 8; t++) { accA[t] += cfa * wa[t]; accB[t] += cfb * wb[t]; }
        }
    }

#pragma unroll
    for (int t = 0; t < 8; t++) {
        atomicAdd(&shA[t * EPB + lane],      accA[t]);
        atomicAdd(&shA[t * EPB + lane + 32], accB[t]);
    }
    __syncthreads();

    for (int i = tid; i < 8 * EPB; i += TBE) {
        int e = i >> 3, o = i & 7;
        if (e0 + e < EI)
            out[(e0 + e) * 8 + o] = PWREC * shA[o * EPB + e];
    }
}

// ---------------------------------------------------------------------------
// host launcher (graph-capturable: kernel launches only)
// ---------------------------------------------------------------------------
extern "C" void kernel_launch(void* const* d_in, const int* in_sizes, int n_in,
                              void* d_out, int out_size) {
    (void)n_in; (void)out_size;
    const float* x       = (const float*)d_in[0];
    const float* pos     = (const float*)d_in[1];
    const int*   eidx    = (const int*)  d_in[2];
    const float* eattr   = (const float*)d_in[3];
    const int*   iidx    = (const int*)  d_in[4];
    const float* emb_w0  = (const float*)d_in[5];
    const float* emb_w1  = (const float*)d_in[6];
    const float* imp0    = (const float*)d_in[7];
    const float* msg0_w0 = (const float*)d_in[8];
    const float* msg0_w1 = (const float*)d_in[9];
    const float* upd0_w0 = (const float*)d_in[10];
    const float* upd0_w1 = (const float*)d_in[11];
    const float* imp1    = (const float*)d_in[12];
    const float* msg1_w0 = (const float*)d_in[13];
    const float* msg1_w1 = (const float*)d_in[14];
    const float* upd1_w0 = (const float*)d_in[15];
    const float* upd1_w1 = (const float*)d_in[16];
    const float* lig_w0  = (const float*)d_in[17];
    const float* lig_w1  = (const float*)d_in[18];
    const float* rec_w0  = (const float*)d_in[19];
    const float* rec_w1  = (const float*)d_in[20];

    int N  = in_sizes[1] / 3;
    int A  = in_sizes[0] / N;
    int E  = in_sizes[2] / 2;
    int B  = in_sizes[3] / E;
    int EI = in_sizes[4] / 2;
    const int* src  = eidx;
    const int* dst  = eidx + E;
    const int* recI = iidx;
    const int* ligI = iidx + EI;
    float degf = (float)E / (float)N;

    int gn = (N + 127) / 128;
    int ge = (E + EPB - 1) / EPB;
    int gi = (EI + EPB - 1) / EPB;

    k_embed<<<gn, 128>>>(x, N, A, emb_w0, emb_w1);      // also zeroes g_msgs

    k_msg<<<ge, TBE>>>(pos, src, dst, eattr, E, B, msg0_w0, msg0_w1);
    k_update<<<gn, 128>>>(N, imp0, degf, upd0_w0, upd0_w1, 1.0f);  // re-zeroes g_msgs

    k_msg<<<ge, TBE>>>(pos, src, dst, eattr, E, B, msg1_w0, msg1_w1);
    k_update<<<gn, 128>>>(N, imp1, degf, upd1_w0, upd1_w1, 0.5f);

    k_lig<<<gi, TBE>>>(pos, recI, ligI, EI, lig_w0, lig_w1);
    k_rec<<<gi, TBE>>>(pos, recI, ligI, EI, rec_w0, rec_w1, (float*)d_out);
}